// round 3
// baseline (speedup 1.0000x reference)
#include <cuda_runtime.h>
#include <cstdint>

#define NN   100000
#define EE   1600000
#define IND  128
#define HIDD 256
#define OUTD 64

// ---------------- scratch (device globals: allocation-free rule) -------------
__device__ int   g_src[EE];               // 6.4 MB
__device__ int   g_dst[EE];               // 6.4 MB
__device__ float g_cnt[NN];
__device__ float g_inv[NN];
__device__ float g_agg1[NN * IND];        // 51.2 MB (becomes mean in-place)
__device__ float g_h[NN * HIDD];          // 102.4 MB
__device__ float g_pq[NN * (2 * OUTD)];   // 51.2 MB  (p | q)
__device__ float g_agg2[NN * OUTD];       // 25.6 MB
__device__ int   g_is64;

// ---------------- index dtype detection + conversion -------------------------
// jnp.int64 in the reference may arrive as int32 (jax x64 disabled) or int64.
// If int64: every high 32-bit word is 0 (values in [0,100000)).
// If int32: the "high words" are just other random indices -> some nonzero.
__global__ void k_detect(const void* __restrict__ ei) {
    __shared__ int s_any;
    if (threadIdx.x == 0) s_any = 0;
    __syncthreads();
    const uint2* p = (const uint2*)ei;
    unsigned any = 0;
    for (int i = threadIdx.x; i < 2048; i += blockDim.x) any |= p[i].y;
    if (any) atomicOr(&s_any, 1);
    __syncthreads();
    if (threadIdx.x == 0) g_is64 = (s_any == 0) ? 1 : 0;
}

__global__ void k_convert(const void* __restrict__ ei) {
    int t = blockIdx.x * blockDim.x + threadIdx.x;
    if (t >= 2 * EE) return;
    int v;
    if (g_is64) v = (int)((const long long*)ei)[t];
    else        v = ((const int*)ei)[t];
    if (t < EE) g_src[t] = v;
    else        g_dst[t - EE] = v;
}

// ---------------- zero accumulators ------------------------------------------
__global__ void k_zero() {
    int t = blockIdx.x * blockDim.x + threadIdx.x;
    const int A1 = NN * (IND / 4);            // agg1 float4 count
    const int A2 = A1 + NN * (OUTD / 4);      // agg2
    const int A3 = A2 + NN / 4;               // cnt
    float4 z = make_float4(0.f, 0.f, 0.f, 0.f);
    if (t < A1)      ((float4*)g_agg1)[t] = z;
    else if (t < A2) ((float4*)g_agg2)[t - A1] = z;
    else if (t < A3) ((float4*)g_cnt)[t - A2] = z;
}

// ---------------- layer-1 scatter: agg1[dst] += x[src], cnt[dst] += 1 --------
// 32 threads per edge, one float4 per thread (128 floats/row).
__global__ void k_scatter1(const float* __restrict__ x) {
    int t = blockIdx.x * blockDim.x + threadIdx.x;
    if (t >= EE * 32) return;
    int e = t >> 5;
    int c = t & 31;
    int s = g_src[e];
    int d = g_dst[e];
    float4 v = ((const float4*)x)[s * 32 + c];
    atomicAdd(((float4*)g_agg1) + (d * 32 + c), v);
    if (c == 0) atomicAdd(&g_cnt[d], 1.0f);
}

// ---------------- mean: agg1 *= 1/max(cnt,1); save inv for layer 2 -----------
__global__ void k_mean() {
    int t = blockIdx.x * blockDim.x + threadIdx.x;
    if (t >= NN * 32) return;
    int i = t >> 5;
    int c = t & 31;
    float inv = 1.0f / fmaxf(g_cnt[i], 1.0f);
    float4* p = ((float4*)g_agg1) + t;
    float4 v = *p;
    v.x *= inv; v.y *= inv; v.z *= inv; v.w *= inv;
    *p = v;
    if (c == 0) g_inv[i] = inv;
}

// ---------------- GEMM1: h = relu([mean|x] @ [W1_l|W1_r]^T + b1) -------------
// M=NN, Ncols=256, K=256. Tile 128x64, BK=16, 128 threads, 8x8 microtile.
__global__ __launch_bounds__(128) void k_gemm1(
    const float* __restrict__ x,
    const float* __restrict__ W1l, const float* __restrict__ W1r,
    const float* __restrict__ b1)
{
    __shared__ float As[16][132];
    __shared__ float Bs[16][68];

    const int m0 = blockIdx.x * 128;
    const int j0 = blockIdx.y * 64;
    const int tid = threadIdx.x;
    const int lk = tid & 3;      // float4 index along k within tile
    const int lr = tid >> 2;     // 0..31
    const int tx = tid & 7;      // col group (8 cols)
    const int ty = tid >> 3;     // row group (8 rows), 0..15

    float acc[8][8];
#pragma unroll
    for (int r = 0; r < 8; r++)
#pragma unroll
        for (int c = 0; c < 8; c++) acc[r][c] = 0.f;

    for (int kt = 0; kt < 256; kt += 16) {
        const float* Ab = (kt < 128) ? (g_agg1 + kt) : (x + (kt - 128));
        const float* Bb = (kt < 128) ? (W1l + kt) : (W1r + (kt - 128));

#pragma unroll
        for (int it = 0; it < 4; it++) {
            int row = lr + 32 * it;
            int gr = m0 + row;
            float4 v = make_float4(0.f, 0.f, 0.f, 0.f);
            if (gr < NN) v = *(const float4*)(Ab + gr * IND + lk * 4);
            As[lk * 4 + 0][row] = v.x;
            As[lk * 4 + 1][row] = v.y;
            As[lk * 4 + 2][row] = v.z;
            As[lk * 4 + 3][row] = v.w;
        }
#pragma unroll
        for (int it = 0; it < 2; it++) {
            int j = lr + 32 * it;  // 0..63
            float4 v = *(const float4*)(Bb + (j0 + j) * IND + lk * 4);
            Bs[lk * 4 + 0][j] = v.x;
            Bs[lk * 4 + 1][j] = v.y;
            Bs[lk * 4 + 2][j] = v.z;
            Bs[lk * 4 + 3][j] = v.w;
        }
        __syncthreads();

#pragma unroll
        for (int kk = 0; kk < 16; kk++) {
            float4 a0 = *(const float4*)&As[kk][ty * 8];
            float4 a1 = *(const float4*)&As[kk][ty * 8 + 4];
            float4 b0 = *(const float4*)&Bs[kk][tx * 8];
            float4 b1v = *(const float4*)&Bs[kk][tx * 8 + 4];
            float a[8] = {a0.x, a0.y, a0.z, a0.w, a1.x, a1.y, a1.z, a1.w};
            float b[8] = {b0.x, b0.y, b0.z, b0.w, b1v.x, b1v.y, b1v.z, b1v.w};
#pragma unroll
            for (int r = 0; r < 8; r++)
#pragma unroll
                for (int c = 0; c < 8; c++)
                    acc[r][c] = fmaf(a[r], b[c], acc[r][c]);
        }
        __syncthreads();
    }

#pragma unroll
    for (int r = 0; r < 8; r++) {
        int gr = m0 + ty * 8 + r;
        if (gr < NN) {
#pragma unroll
            for (int c = 0; c < 8; c++) {
                int gc = j0 + tx * 8 + c;
                float v = acc[r][c] + b1[gc];
                g_h[gr * HIDD + gc] = fmaxf(v, 0.f);
            }
        }
    }
}

// ---------------- GEMM2: pq = h @ [W2_l ; W2_r]^T  (p = cols 0..63, q = 64..127)
__global__ __launch_bounds__(128) void k_gemm2(
    const float* __restrict__ W2l, const float* __restrict__ W2r)
{
    __shared__ float As[16][132];
    __shared__ float Bs[16][68];

    const int m0 = blockIdx.x * 128;
    const float* Bbase = blockIdx.y ? W2r : W2l;   // 64 rows each, K=256
    const int jout = blockIdx.y * 64;
    const int tid = threadIdx.x;
    const int lk = tid & 3;
    const int lr = tid >> 2;
    const int tx = tid & 7;
    const int ty = tid >> 3;

    float acc[8][8];
#pragma unroll
    for (int r = 0; r < 8; r++)
#pragma unroll
        for (int c = 0; c < 8; c++) acc[r][c] = 0.f;

    for (int kt = 0; kt < 256; kt += 16) {
#pragma unroll
        for (int it = 0; it < 4; it++) {
            int row = lr + 32 * it;
            int gr = m0 + row;
            float4 v = make_float4(0.f, 0.f, 0.f, 0.f);
            if (gr < NN) v = *(const float4*)(g_h + gr * HIDD + kt + lk * 4);
            As[lk * 4 + 0][row] = v.x;
            As[lk * 4 + 1][row] = v.y;
            As[lk * 4 + 2][row] = v.z;
            As[lk * 4 + 3][row] = v.w;
        }
#pragma unroll
        for (int it = 0; it < 2; it++) {
            int j = lr + 32 * it;
            float4 v = *(const float4*)(Bbase + j * HIDD + kt + lk * 4);
            Bs[lk * 4 + 0][j] = v.x;
            Bs[lk * 4 + 1][j] = v.y;
            Bs[lk * 4 + 2][j] = v.z;
            Bs[lk * 4 + 3][j] = v.w;
        }
        __syncthreads();

#pragma unroll
        for (int kk = 0; kk < 16; kk++) {
            float4 a0 = *(const float4*)&As[kk][ty * 8];
            float4 a1 = *(const float4*)&As[kk][ty * 8 + 4];
            float4 b0 = *(const float4*)&Bs[kk][tx * 8];
            float4 b1v = *(const float4*)&Bs[kk][tx * 8 + 4];
            float a[8] = {a0.x, a0.y, a0.z, a0.w, a1.x, a1.y, a1.z, a1.w};
            float b[8] = {b0.x, b0.y, b0.z, b0.w, b1v.x, b1v.y, b1v.z, b1v.w};
#pragma unroll
            for (int r = 0; r < 8; r++)
#pragma unroll
                for (int c = 0; c < 8; c++)
                    acc[r][c] = fmaf(a[r], b[c], acc[r][c]);
        }
        __syncthreads();
    }

#pragma unroll
    for (int r = 0; r < 8; r++) {
        int gr = m0 + ty * 8 + r;
        if (gr < NN) {
#pragma unroll
            for (int c = 0; c < 8; c++) {
                int gc = jout + tx * 8 + c;
                g_pq[gr * (2 * OUTD) + gc] = acc[r][c];
            }
        }
    }
}

// ---------------- layer-2 scatter: agg2[dst] += p[src] (64-dim) --------------
// 16 threads per edge, one float4 each.
__global__ void k_scatter2() {
    int t = blockIdx.x * blockDim.x + threadIdx.x;
    if (t >= EE * 16) return;
    int e = t >> 4;
    int c = t & 15;
    int s = g_src[e];
    int d = g_dst[e];
    float4 v = ((const float4*)g_pq)[s * 32 + c];          // p = first 16 float4 of row
    atomicAdd(((float4*)g_agg2) + (d * 16 + c), v);
}

// ---------------- epilogue: out = agg2*inv + b2 + q --------------------------
__global__ void k_final(const float* __restrict__ b2, float* __restrict__ out) {
    int t = blockIdx.x * blockDim.x + threadIdx.x;
    if (t >= NN * 16) return;
    int i = t >> 4;
    int c = t & 15;
    float inv = g_inv[i];
    float4 a = ((const float4*)g_agg2)[t];
    float4 q = ((const float4*)g_pq)[i * 32 + 16 + c];     // q = second half of row
    float4 bb = ((const float4*)b2)[c];
    float4 r;
    r.x = fmaf(a.x, inv, bb.x) + q.x;
    r.y = fmaf(a.y, inv, bb.y) + q.y;
    r.z = fmaf(a.z, inv, bb.z) + q.z;
    r.w = fmaf(a.w, inv, bb.w) + q.w;
    ((float4*)out)[t] = r;
}

// ---------------- launch ------------------------------------------------------
extern "C" void kernel_launch(void* const* d_in, const int* in_sizes, int n_in,
                              void* d_out, int out_size) {
    const float* x   = (const float*)d_in[0];
    const void*  ei  = d_in[1];
    const float* W1l = (const float*)d_in[2];
    const float* b1  = (const float*)d_in[3];
    const float* W1r = (const float*)d_in[4];
    const float* W2l = (const float*)d_in[5];
    const float* b2  = (const float*)d_in[6];
    const float* W2r = (const float*)d_in[7];
    float* out = (float*)d_out;

    k_detect<<<1, 256>>>(ei);
    k_convert<<<(2 * EE + 255) / 256, 256>>>(ei);

    const int zero_elems = NN * (IND / 4) + NN * (OUTD / 4) + NN / 4;
    k_zero<<<(zero_elems + 255) / 256, 256>>>();

    k_scatter1<<<(EE * 32) / 256, 256>>>(x);
    k_mean<<<(NN * 32 + 255) / 256, 256>>>();

    dim3 g1((NN + 127) / 128, HIDD / 64);
    k_gemm1<<<g1, 128>>>(x, W1l, W1r, b1);

    dim3 g2((NN + 127) / 128, (2 * OUTD) / 64);
    k_gemm2<<<g2, 128>>>(W2l, W2r);

    k_scatter2<<<(EE * 16) / 256, 256>>>();
    k_final<<<(NN * 16 + 255) / 256, 256>>>(b2, out);
}